// round 5
// baseline (speedup 1.0000x reference)
#include <cuda_runtime.h>
#include <math.h>

#define Bq 4
#define Aq 16
#define NL 4096
#define DE 256
#define DH 64
#define Hh 8
#define DHEAD 32
#define NBA 64            // B*A
#define INVS 0.17677669529663687f   // 1/sqrt(32)
#define NEG_INF __int_as_float(0xff800000)

// ---------------- scratch (static device memory; no allocation) ----------------
__device__ float g_wv[NBA * Hh * DE];        // 512 KB
__device__ float g_s1[NBA * Hh];
__device__ float g_c0[NBA * Hh];
__device__ float g_scores[NBA * Hh * NL];    // 8 MB  (layout: (b*A+a)*8+h, nl)
__device__ float g_vals[Bq * NL * DH];       // 4 MB
__device__ float g_part[32 * Bq * 128 * DH]; // 4 MB  (kc, b, h*16+a, d)
__device__ float g_ch[NBA * DH];

// ---------------- K1: q projection folded into per-(b,a,h) weight vectors -----
__global__ void __launch_bounds__(256) k1_qwv(
    const float* __restrict__ curr_rho,
    const float* __restrict__ Wq, const float* __restrict__ Wk,
    const float* __restrict__ lnqw, const float* __restrict__ lnqb,
    const float* __restrict__ lnkw, const float* __restrict__ lnkb)
{
    __shared__ float xn[DE];
    __shared__ float qs[DE];
    __shared__ float rs[8], rs2[8], red[8];
    int ba = blockIdx.x;
    int t = threadIdx.x;
    int warp = t >> 5, lane = t & 31;

    float x = curr_rho[ba * DE + t];
    float s = x, s2 = x * x;
#pragma unroll
    for (int off = 16; off; off >>= 1) {
        s  += __shfl_xor_sync(~0u, s, off);
        s2 += __shfl_xor_sync(~0u, s2, off);
    }
    if (lane == 0) { rs[warp] = s; rs2[warp] = s2; }
    __syncthreads();
    float sum = 0.f, ssq = 0.f;
#pragma unroll
    for (int i = 0; i < 8; i++) { sum += rs[i]; ssq += rs2[i]; }
    float mu  = sum * (1.0f / DE);
    float var = ssq * (1.0f / DE) - mu * mu;
    float isg = rsqrtf(var + 1e-5f);
    xn[t] = (x - mu) * isg * lnqw[t] + lnqb[t];
    __syncthreads();

    // q[j] = dot(xn, Wq[j,:]) ; warp 'warp' handles j = warp*32 .. +31 (coalesced Wq reads)
    for (int jj = 0; jj < 32; jj++) {
        int j = warp * 32 + jj;
        float acc = 0.f;
#pragma unroll
        for (int k = 0; k < 8; k++)
            acc += xn[lane + 32 * k] * Wq[j * DE + lane + 32 * k];
#pragma unroll
        for (int off = 16; off; off >>= 1) acc += __shfl_xor_sync(~0u, acc, off);
        if (lane == 0) qs[j] = acc;
    }
    __syncthreads();

    // wvec[h][e=t] = sum_d q[h*32+d] * Wk[(h*32+d), e]   (coalesced over e=t)
    float wvh[Hh], c0h[Hh];
    float lw = lnkw[t], lb = lnkb[t];
#pragma unroll
    for (int h = 0; h < Hh; h++) {
        float acc = 0.f;
        for (int d = 0; d < DHEAD; d++)
            acc += qs[h * DHEAD + d] * Wk[(h * DHEAD + d) * DE + t];
        float wv = acc * lw * INVS;
        g_wv[(ba * Hh + h) * DE + t] = wv;
        wvh[h] = wv;
        c0h[h] = acc * lb * INVS;
    }
    // block reductions for s1[h], c0[h]
    for (int h = 0; h < Hh; h++) {
        float v = wvh[h];
#pragma unroll
        for (int off = 16; off; off >>= 1) v += __shfl_xor_sync(~0u, v, off);
        __syncthreads();
        if (lane == 0) red[warp] = v;
        __syncthreads();
        if (t == 0) { float q = 0.f; for (int i = 0; i < 8; i++) q += red[i]; g_s1[ba * Hh + h] = q; }
        v = c0h[h];
#pragma unroll
        for (int off = 16; off; off >>= 1) v += __shfl_xor_sync(~0u, v, off);
        __syncthreads();
        if (lane == 0) red[warp] = v;
        __syncthreads();
        if (t == 0) { float q = 0.f; for (int i = 0; i < 8; i++) q += red[i]; g_c0[ba * Hh + h] = q; }
    }
}

// ---------------- K_vals: logmap0(demo_hyp)  (warp per 64-wide row) -----------
__global__ void __launch_bounds__(256) k_vals(const float* __restrict__ demo_hyp)
{
    int row  = blockIdx.x * 8 + (threadIdx.x >> 5);   // 0 .. B*NL-1
    int lane = threadIdx.x & 31;
    const float* p = demo_hyp + (size_t)row * DH;
    float x0 = p[lane], x1 = p[lane + 32];
    float ss = x0 * x0 + x1 * x1;
#pragma unroll
    for (int off = 16; off; off >>= 1) ss += __shfl_xor_sync(~0u, ss, off);
    float n = fmaxf(sqrtf(ss), 1e-15f);
    float u = fminf(n, 1.0f - 1e-5f);
    float sc = atanhf(u) / n;
    g_vals[(size_t)row * DH + lane]      = x0 * sc;
    g_vals[(size_t)row * DH + lane + 32] = x1 * sc;
}

// ---------------- K2: main pass (LN + 8 dots per demo row, wv in registers) ---
#define CHUNK 256
__global__ void __launch_bounds__(256) k2_scores(
    const float* __restrict__ demo_rho, const int* __restrict__ demo_mask)
{
    int ba = blockIdx.x;
    int b = ba >> 4, a = ba & 15;
    int warp = threadIdx.x >> 5, lane = threadIdx.x & 31;

    // wv registers: e-slot mapping k<4 -> e=4*lane+k ; k>=4 -> e=128+4*lane+(k-4)
    float wv[8][8];
    const float* wp = g_wv + ba * (Hh * DE);
#pragma unroll
    for (int h = 0; h < 8; h++) {
        float4 v0 = *(const float4*)(wp + h * DE + 4 * lane);
        float4 v1 = *(const float4*)(wp + h * DE + 128 + 4 * lane);
        wv[h][0] = v0.x; wv[h][1] = v0.y; wv[h][2] = v0.z; wv[h][3] = v0.w;
        wv[h][4] = v1.x; wv[h][5] = v1.y; wv[h][6] = v1.z; wv[h][7] = v1.w;
    }
    float s1[8], c0[8];
#pragma unroll
    for (int h = 0; h < 8; h++) { s1[h] = g_s1[ba * 8 + h]; c0[h] = g_c0[ba * 8 + h]; }

    int r0 = blockIdx.y * CHUNK;
    for (int r = r0 + warp; r < r0 + CHUNK; r += 8) {
        const float* xp = demo_rho + ((size_t)(b * NL + r) * Aq + a) * DE;
        float4 x0 = *(const float4*)(xp + 4 * lane);
        float4 x1 = *(const float4*)(xp + 128 + 4 * lane);
        float xs[8] = {x0.x, x0.y, x0.z, x0.w, x1.x, x1.y, x1.z, x1.w};
        float sum = 0.f, ssq = 0.f, acc[8];
#pragma unroll
        for (int h = 0; h < 8; h++) acc[h] = 0.f;
#pragma unroll
        for (int k = 0; k < 8; k++) {
            float xv = xs[k];
            sum += xv; ssq += xv * xv;
#pragma unroll
            for (int h = 0; h < 8; h++) acc[h] += xv * wv[h][k];
        }
#pragma unroll
        for (int off = 16; off; off >>= 1) {
            sum += __shfl_xor_sync(~0u, sum, off);
            ssq += __shfl_xor_sync(~0u, ssq, off);
#pragma unroll
            for (int h = 0; h < 8; h++) acc[h] += __shfl_xor_sync(~0u, acc[h], off);
        }
        if (lane == 0) {
            float mu  = sum * (1.0f / DE);
            float var = ssq * (1.0f / DE) - mu * mu;
            float isg = rsqrtf(var + 1e-5f);
            int mk = demo_mask[b * NL + r];
            float* op = g_scores + (size_t)ba * Hh * NL + r;
#pragma unroll
            for (int h = 0; h < 8; h++) {
                float sc = (mk == 0) ? NEG_INF : (acc[h] - mu * s1[h]) * isg + c0[h];
                op[(size_t)h * NL] = sc;
            }
        }
    }
}

// ---------------- K3: softmax over NL=4096, write attn into d_out -------------
__global__ void __launch_bounds__(256) k3_softmax(float* __restrict__ d_out)
{
    int row = blockIdx.x;            // (b*A+a)*8 + h   ; 512 rows total
    int ba = row >> 3, h = row & 7;
    int b = ba >> 4, a = ba & 15;
    const float* sp = g_scores + (size_t)row * NL;
    float* op = d_out + 256 + (size_t)((b * Hh + h) * Aq + a) * NL;
    int t = threadIdx.x;
    __shared__ float red[8];

    float v[16]; float mx = NEG_INF;
#pragma unroll
    for (int i = 0; i < 16; i++) { v[i] = sp[t + 256 * i]; mx = fmaxf(mx, v[i]); }
#pragma unroll
    for (int off = 16; off; off >>= 1) mx = fmaxf(mx, __shfl_xor_sync(~0u, mx, off));
    if ((t & 31) == 0) red[t >> 5] = mx;
    __syncthreads();
    mx = red[0];
#pragma unroll
    for (int i = 1; i < 8; i++) mx = fmaxf(mx, red[i]);

    float s = 0.f;
    bool dead = (mx == NEG_INF);
#pragma unroll
    for (int i = 0; i < 16; i++) { float e = dead ? 0.f : expf(v[i] - mx); v[i] = e; s += e; }
#pragma unroll
    for (int off = 16; off; off >>= 1) s += __shfl_xor_sync(~0u, s, off);
    __syncthreads();
    if ((t & 31) == 0) red[t >> 5] = s;
    __syncthreads();
    s = 0.f;
#pragma unroll
    for (int i = 0; i < 8; i++) s += red[i];
    float r = (s > 0.f) ? 1.0f / s : 0.f;
#pragma unroll
    for (int i = 0; i < 16; i++) op[t + 256 * i] = v[i] * r;
}

// ---------------- K4: m_h partials = attn @ vals (split-K, deterministic) -----
#define KC 128
__global__ void __launch_bounds__(256) k4_mh(const float* __restrict__ d_attn)
{
    int b  = blockIdx.x & 3;
    int kc = blockIdx.x >> 2;        // 0..31
    __shared__ float vals_s[KC * DH];   // 32 KB
    __shared__ float attn_s[16 * KC];   // 8 KB
    int tid = threadIdx.x;

    const float* vp = g_vals + (size_t)(b * NL + kc * KC) * DH;
#pragma unroll
    for (int i = 0; i < 32; i++) vals_s[tid + 256 * i] = vp[tid + 256 * i];

    int c = tid & 63, rs = tid >> 6;  // rs in 0..3
    for (int rgg = 0; rgg < 8; rgg++) {
        __syncthreads();
#pragma unroll
        for (int i = 0; i < 8; i++) {
            int lin = tid + 256 * i;
            int rr = lin >> 7, kk = lin & 127;
            attn_s[lin] = d_attn[(size_t)(b * 128 + rgg * 16 + rr) * NL + kc * KC + kk];
        }
        __syncthreads();
        float a0 = 0.f, a1 = 0.f, a2 = 0.f, a3 = 0.f;
#pragma unroll 4
        for (int k = 0; k < KC; k++) {
            float v = vals_s[k * DH + c];
            a0 += attn_s[(rs * 4 + 0) * KC + k] * v;
            a1 += attn_s[(rs * 4 + 1) * KC + k] * v;
            a2 += attn_s[(rs * 4 + 2) * KC + k] * v;
            a3 += attn_s[(rs * 4 + 3) * KC + k] * v;
        }
        int rbase = rgg * 16 + rs * 4;
        float* pp = g_part + ((size_t)(kc * 4 + b) * 128 + rbase) * DH + c;
        pp[0 * DH] = a0; pp[1 * DH] = a1; pp[2 * DH] = a2; pp[3 * DH] = a3;
    }
}

// ---------------- K5: reduce partials + hyperbolic epilogue per (b,a) ---------
__global__ void __launch_bounds__(64) k5_epi()
{
    int ba = blockIdx.x; int b = ba >> 4, a = ba & 15;
    int d = threadIdx.x;
    __shared__ float s2[2];
    float ymean = 0.f;
    for (int h = 0; h < 8; h++) {
        int r = h * 16 + a;
        float m = 0.f;
        for (int kc = 0; kc < 32; kc++)
            m += g_part[((size_t)(kc * 4 + b) * 128 + r) * DH + d];
        // expmap0
        float v = m * m;
#pragma unroll
        for (int off = 16; off; off >>= 1) v += __shfl_xor_sync(~0u, v, off);
        __syncthreads();
        if ((d & 31) == 0) s2[d >> 5] = v;
        __syncthreads();
        float n1 = fmaxf(sqrtf(s2[0] + s2[1]), 1e-15f);
        float vd = tanhf(n1) * m / n1;
        // logmap0
        v = vd * vd;
#pragma unroll
        for (int off = 16; off; off >>= 1) v += __shfl_xor_sync(~0u, v, off);
        __syncthreads();
        if ((d & 31) == 0) s2[d >> 5] = v;
        __syncthreads();
        float nv = fmaxf(sqrtf(s2[0] + s2[1]), 1e-15f);
        float u = fminf(nv, 1.0f - 1e-5f);
        ymean += atanhf(u) * vd / nv;
    }
    ymean *= 0.125f;
    // expmap0
    float v = ymean * ymean;
#pragma unroll
    for (int off = 16; off; off >>= 1) v += __shfl_xor_sync(~0u, v, off);
    __syncthreads();
    if ((d & 31) == 0) s2[d >> 5] = v;
    __syncthreads();
    float n = fmaxf(sqrtf(s2[0] + s2[1]), 1e-15f);
    float ch = tanhf(n) * ymean / n;
    // radius clamp
    v = ch * ch;
#pragma unroll
    for (int off = 16; off; off >>= 1) v += __shfl_xor_sync(~0u, v, off);
    __syncthreads();
    if ((d & 31) == 0) s2[d >> 5] = v;
    __syncthreads();
    float cn = fmaxf(sqrtf(s2[0] + s2[1]), 1e-6f);
    ch *= fminf((1.0f - 1e-5f) / cn, 1.0f);
    g_ch[ba * DH + d] = ch;
}

// ---------------- K6: mean over A -> d_out[0:256] -----------------------------
__global__ void __launch_bounds__(256) k6_out(float* __restrict__ d_out)
{
    int t = threadIdx.x;           // 256 = B*DH
    int b = t >> 6, d = t & 63;
    float s = 0.f;
#pragma unroll
    for (int a = 0; a < 16; a++) s += g_ch[(b * 16 + a) * DH + d];
    d_out[t] = s * (1.0f / 16.0f);
}

// ---------------- launcher ----------------------------------------------------
extern "C" void kernel_launch(void* const* d_in, const int* in_sizes, int n_in,
                              void* d_out, int out_size)
{
    const float* curr_rho  = (const float*)d_in[0];
    const float* demo_rho  = (const float*)d_in[1];
    const float* demo_hyp  = (const float*)d_in[2];
    const int*   demo_mask = (const int*)  d_in[3];
    const float* Wq        = (const float*)d_in[4];
    const float* Wk        = (const float*)d_in[5];
    const float* lnqw      = (const float*)d_in[6];
    const float* lnqb      = (const float*)d_in[7];
    const float* lnkw      = (const float*)d_in[8];
    const float* lnkb      = (const float*)d_in[9];
    float* out = (float*)d_out;

    k1_qwv<<<64, 256>>>(curr_rho, Wq, Wk, lnqw, lnqb, lnkw, lnkb);
    k_vals<<<2048, 256>>>(demo_hyp);
    k2_scores<<<dim3(64, 16), 256>>>(demo_rho, demo_mask);
    k3_softmax<<<512, 256>>>(out);
    k4_mh<<<128, 256>>>(out + 256);
    k5_epi<<<64, 64>>>();
    k6_out<<<1, 256>>>(out);
}

// round 8
// speedup vs baseline: 1.2373x; 1.2373x over previous
#include <cuda_runtime.h>
#include <math.h>

#define Bq 4
#define Aq 16
#define NL 4096
#define DE 256
#define DH 64
#define Hh 8
#define DHEAD 32
#define NBA 64            // B*A
#define INVS 0.17677669529663687f   // 1/sqrt(32)
#define NEG_INF __int_as_float(0xff800000)

// ---------------- scratch (static device memory; no allocation) ----------------
__device__ float g_wv[NBA * Hh * DE];        // 512 KB
__device__ float g_s1[NBA * Hh];
__device__ float g_c0[NBA * Hh];
__device__ float g_scores[NBA * Hh * NL];    // 8 MB  (layout: (b*A+a)*8+h, nl)
__device__ float g_vals[Bq * NL * DH];       // 4 MB
__device__ float g_part[32 * Bq * 128 * DH]; // 4 MB  (kc, b, h*16+a, d)
__device__ float g_ch[NBA * DH];

// ---------------- K1: q projection folded into per-(b,a,h) weight vectors -----
__global__ void __launch_bounds__(256) k1_qwv(
    const float* __restrict__ curr_rho,
    const float* __restrict__ Wq, const float* __restrict__ Wk,
    const float* __restrict__ lnqw, const float* __restrict__ lnqb,
    const float* __restrict__ lnkw, const float* __restrict__ lnkb)
{
    __shared__ float xn[DE];
    __shared__ float qs[DE];
    __shared__ float rs[8], rs2[8], red[8];
    int ba = blockIdx.x;
    int t = threadIdx.x;
    int warp = t >> 5, lane = t & 31;

    float x = curr_rho[ba * DE + t];
    float s = x, s2 = x * x;
#pragma unroll
    for (int off = 16; off; off >>= 1) {
        s  += __shfl_xor_sync(~0u, s, off);
        s2 += __shfl_xor_sync(~0u, s2, off);
    }
    if (lane == 0) { rs[warp] = s; rs2[warp] = s2; }
    __syncthreads();
    float sum = 0.f, ssq = 0.f;
#pragma unroll
    for (int i = 0; i < 8; i++) { sum += rs[i]; ssq += rs2[i]; }
    float mu  = sum * (1.0f / DE);
    float var = ssq * (1.0f / DE) - mu * mu;
    float isg = rsqrtf(var + 1e-5f);
    xn[t] = (x - mu) * isg * lnqw[t] + lnqb[t];
    __syncthreads();

    // q[j] = dot(xn, Wq[j,:])
    for (int jj = 0; jj < 32; jj++) {
        int j = warp * 32 + jj;
        float acc = 0.f;
#pragma unroll
        for (int k = 0; k < 8; k++)
            acc += xn[lane + 32 * k] * Wq[j * DE + lane + 32 * k];
#pragma unroll
        for (int off = 16; off; off >>= 1) acc += __shfl_xor_sync(~0u, acc, off);
        if (lane == 0) qs[j] = acc;
    }
    __syncthreads();

    // wvec[h][e=t] = sum_d q[h*32+d] * Wk[(h*32+d), e]
    float wvh[Hh], c0h[Hh];
    float lw = lnkw[t], lb = lnkb[t];
#pragma unroll
    for (int h = 0; h < Hh; h++) {
        float acc = 0.f;
        for (int d = 0; d < DHEAD; d++)
            acc += qs[h * DHEAD + d] * Wk[(h * DHEAD + d) * DE + t];
        float wv = acc * lw * INVS;
        g_wv[(ba * Hh + h) * DE + t] = wv;
        wvh[h] = wv;
        c0h[h] = acc * lb * INVS;
    }
    for (int h = 0; h < Hh; h++) {
        float v = wvh[h];
#pragma unroll
        for (int off = 16; off; off >>= 1) v += __shfl_xor_sync(~0u, v, off);
        __syncthreads();
        if (lane == 0) red[warp] = v;
        __syncthreads();
        if (t == 0) { float q = 0.f; for (int i = 0; i < 8; i++) q += red[i]; g_s1[ba * Hh + h] = q; }
        v = c0h[h];
#pragma unroll
        for (int off = 16; off; off >>= 1) v += __shfl_xor_sync(~0u, v, off);
        __syncthreads();
        if (lane == 0) red[warp] = v;
        __syncthreads();
        if (t == 0) { float q = 0.f; for (int i = 0; i < 8; i++) q += red[i]; g_c0[ba * Hh + h] = q; }
    }
}

// ---------------- K_vals: logmap0(demo_hyp)  (warp per 64-wide row) -----------
__global__ void __launch_bounds__(256) k_vals(const float* __restrict__ demo_hyp)
{
    int row  = blockIdx.x * 8 + (threadIdx.x >> 5);   // 0 .. B*NL-1
    int lane = threadIdx.x & 31;
    const float* p = demo_hyp + (size_t)row * DH;
    float x0 = p[lane], x1 = p[lane + 32];
    float ss = x0 * x0 + x1 * x1;
#pragma unroll
    for (int off = 16; off; off >>= 1) ss += __shfl_xor_sync(~0u, ss, off);
    float n = fmaxf(sqrtf(ss), 1e-15f);
    float u = fminf(n, 1.0f - 1e-5f);
    float sc = atanhf(u) / n;
    g_vals[(size_t)row * DH + lane]      = x0 * sc;
    g_vals[(size_t)row * DH + lane + 32] = x1 * sc;
}

// ---------------- K2: main pass, 4-deep software pipeline ---------------------
#define CHUNK 256
__global__ void __launch_bounds__(256, 1) k2_scores(
    const float* __restrict__ demo_rho, const int* __restrict__ demo_mask)
{
    int ba = blockIdx.x;
    int b = ba >> 4, a = ba & 15;
    int warp = threadIdx.x >> 5, lane = threadIdx.x & 31;

    // wv registers: e-slot mapping k<4 -> e=4*lane+k ; k>=4 -> e=128+4*lane+(k-4)
    float wv[8][8];
    const float* wp = g_wv + ba * (Hh * DE);
#pragma unroll
    for (int h = 0; h < 8; h++) {
        float4 v0 = *(const float4*)(wp + h * DE + 4 * lane);
        float4 v1 = *(const float4*)(wp + h * DE + 128 + 4 * lane);
        wv[h][0] = v0.x; wv[h][1] = v0.y; wv[h][2] = v0.z; wv[h][3] = v0.w;
        wv[h][4] = v1.x; wv[h][5] = v1.y; wv[h][6] = v1.z; wv[h][7] = v1.w;
    }
    float s1[8], c0[8];
#pragma unroll
    for (int h = 0; h < 8; h++) { s1[h] = g_s1[ba * 8 + h]; c0[h] = g_c0[ba * 8 + h]; }

    int rw = blockIdx.y * CHUNK + warp * 32;           // this warp's 32 rows
    const float* rp = demo_rho + ((size_t)(b * NL + rw)) * (Aq * DE) + a * DE;
    const int* mp = demo_mask + b * NL + rw;
    float* ob = g_scores + (size_t)ba * Hh * NL + rw;

    // preload 4 rows (8 LDG.128 in flight per warp)
    float4 xb0[4], xb1[4];
#pragma unroll
    for (int i = 0; i < 4; i++) {
        const float* p = rp + (size_t)i * (Aq * DE);
        xb0[i] = *(const float4*)(p + 4 * lane);
        xb1[i] = *(const float4*)(p + 128 + 4 * lane);
    }

#pragma unroll 4
    for (int i = 0; i < 32; i++) {
        float4 y0 = xb0[i & 3], y1 = xb1[i & 3];
        int mk = mp[i];
        if (i < 28) {   // prefetch row i+4 into the slot just freed
            const float* p = rp + (size_t)(i + 4) * (Aq * DE);
            xb0[i & 3] = *(const float4*)(p + 4 * lane);
            xb1[i & 3] = *(const float4*)(p + 128 + 4 * lane);
        }
        float xs[8] = {y0.x, y0.y, y0.z, y0.w, y1.x, y1.y, y1.z, y1.w};
        float sum = 0.f, ssq = 0.f, acc[8];
#pragma unroll
        for (int h = 0; h < 8; h++) acc[h] = 0.f;
#pragma unroll
        for (int k = 0; k < 8; k++) {
            float xv = xs[k];
            sum += xv; ssq += xv * xv;
#pragma unroll
            for (int h = 0; h < 8; h++) acc[h] += xv * wv[h][k];
        }
#pragma unroll
        for (int off = 16; off; off >>= 1) {
            sum += __shfl_xor_sync(~0u, sum, off);
            ssq += __shfl_xor_sync(~0u, ssq, off);
#pragma unroll
            for (int h = 0; h < 8; h++) acc[h] += __shfl_xor_sync(~0u, acc[h], off);
        }
        // all lanes hold full sums; lanes 0..7 each store one h in a single STG
        float mu  = sum * (1.0f / DE);
        float var = ssq * (1.0f / DE) - mu * mu;
        float isg = rsqrtf(var + 1e-5f);
        float outv = 0.f;
#pragma unroll
        for (int h = 0; h < 8; h++) {
            float sc = (acc[h] - mu * s1[h]) * isg + c0[h];
            if (lane == h) outv = sc;
        }
        if (lane < 8)
            ob[(size_t)lane * NL + i] = (mk == 0) ? NEG_INF : outv;
    }
}

// ---------------- K3: softmax over NL=4096, write attn into d_out -------------
__global__ void __launch_bounds__(256) k3_softmax(float* __restrict__ d_out)
{
    int row = blockIdx.x;            // (b*A+a)*8 + h   ; 512 rows total
    int ba = row >> 3, h = row & 7;
    int b = ba >> 4, a = ba & 15;
    const float* sp = g_scores + (size_t)row * NL;
    float* op = d_out + 256 + (size_t)((b * Hh + h) * Aq + a) * NL;
    int t = threadIdx.x;
    __shared__ float red[8];

    float v[16]; float mx = NEG_INF;
#pragma unroll
    for (int i = 0; i < 16; i++) { v[i] = sp[t + 256 * i]; mx = fmaxf(mx, v[i]); }
#pragma unroll
    for (int off = 16; off; off >>= 1) mx = fmaxf(mx, __shfl_xor_sync(~0u, mx, off));
    if ((t & 31) == 0) red[t >> 5] = mx;
    __syncthreads();
    mx = red[0];
#pragma unroll
    for (int i = 1; i < 8; i++) mx = fmaxf(mx, red[i]);

    float s = 0.f;
    bool dead = (mx == NEG_INF);
#pragma unroll
    for (int i = 0; i < 16; i++) { float e = dead ? 0.f : expf(v[i] - mx); v[i] = e; s += e; }
#pragma unroll
    for (int off = 16; off; off >>= 1) s += __shfl_xor_sync(~0u, s, off);
    __syncthreads();
    if ((t & 31) == 0) red[t >> 5] = s;
    __syncthreads();
    s = 0.f;
#pragma unroll
    for (int i = 0; i < 8; i++) s += red[i];
    float r = (s > 0.f) ? 1.0f / s : 0.f;
#pragma unroll
    for (int i = 0; i < 16; i++) op[t + 256 * i] = v[i] * r;
}

// ---------------- K4: m_h partials = attn @ vals (split-K, k-blocked) ---------
#define KC 128
#define APAD 132
__global__ void __launch_bounds__(256) k4_mh(const float* __restrict__ d_attn)
{
    int b  = blockIdx.x & 3;
    int kc = blockIdx.x >> 2;        // 0..31
    __shared__ __align__(16) float vals_s[KC * DH];    // 32 KB, [k][c]
    __shared__ __align__(16) float attn_s[16 * APAD];  // padded rows
    int tid = threadIdx.x;

    const float* vp = g_vals + (size_t)(b * NL + kc * KC) * DH;
#pragma unroll
    for (int i = 0; i < 8; i++)
        ((float4*)vals_s)[tid + 256 * i] = ((const float4*)vp)[tid + 256 * i];

    int c = tid & 63, rs = tid >> 6;  // rs in 0..3

    // register double-buffer for attn staging (8 floats/thread per rgg)
    float st[8];
    {
        const float* ap = d_attn + (size_t)(b * 128) * NL + kc * KC;
#pragma unroll
        for (int i = 0; i < 8; i++) {
            int lin = tid + 256 * i;
            st[i] = ap[(size_t)(lin >> 7) * NL + (lin & 127)];
        }
    }
    for (int rgg = 0; rgg < 8; rgg++) {
        __syncthreads();
#pragma unroll
        for (int i = 0; i < 8; i++) {
            int lin = tid + 256 * i;
            attn_s[(lin >> 7) * APAD + (lin & 127)] = st[i];
        }
        __syncthreads();
        if (rgg < 7) {
            const float* ap = d_attn + (size_t)(b * 128 + (rgg + 1) * 16) * NL + kc * KC;
#pragma unroll
            for (int i = 0; i < 8; i++) {
                int lin = tid + 256 * i;
                st[i] = ap[(size_t)(lin >> 7) * NL + (lin & 127)];
            }
        }
        float a0 = 0.f, a1 = 0.f, a2 = 0.f, a3 = 0.f;
#pragma unroll 2
        for (int k4 = 0; k4 < 32; k4++) {
            float4 t0 = *(const float4*)&attn_s[(rs * 4 + 0) * APAD + 4 * k4];
            float4 t1 = *(const float4*)&attn_s[(rs * 4 + 1) * APAD + 4 * k4];
            float4 t2 = *(const float4*)&attn_s[(rs * 4 + 2) * APAD + 4 * k4];
            float4 t3 = *(const float4*)&attn_s[(rs * 4 + 3) * APAD + 4 * k4];
            float v0 = vals_s[(4 * k4 + 0) * DH + c];
            float v1 = vals_s[(4 * k4 + 1) * DH + c];
            float v2 = vals_s[(4 * k4 + 2) * DH + c];
            float v3 = vals_s[(4 * k4 + 3) * DH + c];
            a0 += t0.x * v0; a1 += t1.x * v0; a2 += t2.x * v0; a3 += t3.x * v0;
            a0 += t0.y * v1; a1 += t1.y * v1; a2 += t2.y * v1; a3 += t3.y * v1;
            a0 += t0.z * v2; a1 += t1.z * v2; a2 += t2.z * v2; a3 += t3.z * v2;
            a0 += t0.w * v3; a1 += t1.w * v3; a2 += t2.w * v3; a3 += t3.w * v3;
        }
        int rbase = rgg * 16 + rs * 4;
        float* pp = g_part + ((size_t)(kc * 4 + b) * 128 + rbase) * DH + c;
        pp[0 * DH] = a0; pp[1 * DH] = a1; pp[2 * DH] = a2; pp[3 * DH] = a3;
    }
}

// ---------------- K5: reduce partials + hyperbolic epilogue per (b,a) ---------
__global__ void __launch_bounds__(64) k5_epi()
{
    int ba = blockIdx.x; int b = ba >> 4, a = ba & 15;
    int d = threadIdx.x;
    __shared__ float s2[2];
    float ymean = 0.f;
    for (int h = 0; h < 8; h++) {
        int r = h * 16 + a;
        float m = 0.f;
        for (int kc = 0; kc < 32; kc++)
            m += g_part[((size_t)(kc * 4 + b) * 128 + r) * DH + d];
        float v = m * m;
#pragma unroll
        for (int off = 16; off; off >>= 1) v += __shfl_xor_sync(~0u, v, off);
        __syncthreads();
        if ((d & 31) == 0) s2[d >> 5] = v;
        __syncthreads();
        float n1 = fmaxf(sqrtf(s2[0] + s2[1]), 1e-15f);
        float vd = tanhf(n1) * m / n1;
        v = vd * vd;
#pragma unroll
        for (int off = 16; off; off >>= 1) v += __shfl_xor_sync(~0u, v, off);
        __syncthreads();
        if ((d & 31) == 0) s2[d >> 5] = v;
        __syncthreads();
        float nv = fmaxf(sqrtf(s2[0] + s2[1]), 1e-15f);
        float u = fminf(nv, 1.0f - 1e-5f);
        ymean += atanhf(u) * vd / nv;
    }
    ymean *= 0.125f;
    float v = ymean * ymean;
#pragma unroll
    for (int off = 16; off; off >>= 1) v += __shfl_xor_sync(~0u, v, off);
    __syncthreads();
    if ((d & 31) == 0) s2[d >> 5] = v;
    __syncthreads();
    float n = fmaxf(sqrtf(s2[0] + s2[1]), 1e-15f);
    float ch = tanhf(n) * ymean / n;
    v = ch * ch;
#pragma unroll
    for (int off = 16; off; off >>= 1) v += __shfl_xor_sync(~0u, v, off);
    __syncthreads();
    if ((d & 31) == 0) s2[d >> 5] = v;
    __syncthreads();
    float cn = fmaxf(sqrtf(s2[0] + s2[1]), 1e-6f);
    ch *= fminf((1.0f - 1e-5f) / cn, 1.0f);
    g_ch[ba * DH + d] = ch;
}

// ---------------- K6: mean over A -> d_out[0:256] -----------------------------
__global__ void __launch_bounds__(256) k6_out(float* __restrict__ d_out)
{
    int t = threadIdx.x;           // 256 = B*DH
    int b = t >> 6, d = t & 63;
    float s = 0.f;
#pragma unroll
    for (int a = 0; a < 16; a++) s += g_ch[(b * 16 + a) * DH + d];
    d_out[t] = s * (1.0f / 16.0f);
}

// ---------------- launcher ----------------------------------------------------
extern "C" void kernel_launch(void* const* d_in, const int* in_sizes, int n_in,
                              void* d_out, int out_size)
{
    const float* curr_rho  = (const float*)d_in[0];
    const float* demo_rho  = (const float*)d_in[1];
    const float* demo_hyp  = (const float*)d_in[2];
    const int*   demo_mask = (const int*)  d_in[3];
    const float* Wq        = (const float*)d_in[4];
    const float* Wk        = (const float*)d_in[5];
    const float* lnqw      = (const float*)d_in[6];
    const float* lnqb      = (const float*)d_in[7];
    const float* lnkw      = (const float*)d_in[8];
    const float* lnkb      = (const float*)d_in[9];
    float* out = (float*)d_out;

    k1_qwv<<<64, 256>>>(curr_rho, Wq, Wk, lnqw, lnqb, lnkw, lnkb);
    k_vals<<<2048, 256>>>(demo_hyp);
    k2_scores<<<dim3(64, 16), 256>>>(demo_rho, demo_mask);
    k3_softmax<<<512, 256>>>(out);
    k4_mh<<<128, 256>>>(out + 256);
    k5_epi<<<64, 64>>>();
    k6_out<<<1, 256>>>(out);
}